// round 1
// baseline (speedup 1.0000x reference)
#include <cuda_runtime.h>
#include <cuda_bf16.h>
#include <cstring>

// Problem constants
#define IMG      224
#define P        (IMG*IMG)          // 50176 pixels
#define NB       64                 // batch
#define NR       16                 // rings
#define TD       256                // token dim
#define OD       192                // out dim

// Ring list capacity (largest ring ~4774 pixels)
#define RING_CAP 5120
// Segmented-GEMM tiling
#define KCHUNK   256                // pixels per work unit
#define KT       32                 // K sub-tile
#define BM       64                 // all of batch
#define BN       128                // d tile (2 tiles cover 256)
#define NT       2
#define MAXU     (NR * ((RING_CAP + KCHUNK - 1) / KCHUNK))   // worst-case units = 320

// ---------------- device scratch (static; no allocations allowed) ----------------
__device__ int   g_ring_idx[NR][RING_CAP];
__device__ int   g_ring_count[NR];
__device__ int   g_unit_ring[MAXU];
__device__ int   g_unit_s0[MAXU];
__device__ int   g_ring_ustart[NR];
__device__ int   g_ring_uend[NR];
__device__ int   g_n_units;
__device__ float g_part[MAXU * NT * BM * BN];       // per-unit partial tokens
__device__ float g_tokens[NB * NR * TD];            // reduced tokens

// ---------------- helpers ----------------
__device__ __forceinline__ unsigned long long pack2(float lo, float hi) {
    unsigned long long r;
    asm("mov.b64 %0, {%1, %2};" : "=l"(r) : "f"(lo), "f"(hi));
    return r;
}
__device__ __forceinline__ float2 unpack2(unsigned long long v) {
    float2 f;
    asm("mov.b64 {%0, %1}, %2;" : "=f"(f.x), "=f"(f.y) : "l"(v));
    return f;
}
__device__ __forceinline__ void fma2(unsigned long long& acc,
                                     unsigned long long a,
                                     unsigned long long b) {
    asm("fma.rn.f32x2 %0, %1, %2, %0;" : "+l"(acc) : "l"(a), "l"(b));
}

// ---------------- K1: build stable per-ring pixel index lists ----------------
__global__ __launch_bounds__(1024) void k_build_rings(const float* __restrict__ masks) {
    const int c = blockIdx.x;
    const float* m = masks + (size_t)c * P;
    __shared__ int s_wcnt[32];
    __shared__ int s_woff[33];
    __shared__ int s_base;
    if (threadIdx.x == 0) s_base = 0;
    __syncthreads();
    const int lane = threadIdx.x & 31;
    const int warp = threadIdx.x >> 5;
    for (int start = 0; start < P; start += 1024) {
        int p = start + (int)threadIdx.x;
        bool in = (p < P) && (m[p] != 0.0f);
        unsigned ball = __ballot_sync(0xFFFFFFFFu, in);
        if (lane == 0) s_wcnt[warp] = __popc(ball);
        __syncthreads();
        if (threadIdx.x == 0) {
            int acc = 0;
            for (int w = 0; w < 32; w++) { s_woff[w] = acc; acc += s_wcnt[w]; }
            s_woff[32] = acc;
        }
        __syncthreads();
        if (in) {
            int rank = s_base + s_woff[warp] + __popc(ball & ((1u << lane) - 1u));
            if (rank < RING_CAP) g_ring_idx[c][rank] = p;
        }
        __syncthreads();
        if (threadIdx.x == 0) s_base += s_woff[32];
        __syncthreads();
    }
    if (threadIdx.x == 0) {
        int n = s_base;
        g_ring_count[c] = (n < RING_CAP) ? n : RING_CAP;
    }
}

// ---------------- K2: build work-unit table ----------------
__global__ void k_build_units() {
    int n = 0;
    for (int c = 0; c < NR; c++) {
        g_ring_ustart[c] = n;
        int nc = g_ring_count[c];
        for (int s = 0; s < nc && n < MAXU; s += KCHUNK) {
            g_unit_ring[n] = c;
            g_unit_s0[n]   = s;
            n++;
        }
        g_ring_uend[c] = n;
    }
    g_n_units = n;
}

// ---------------- K3: segmented GEMM (f32x2 microkernel) ----------------
// grid: (MAXU, NT), block: 128 threads. Thread tile 8(b) x 8(d).
__global__ __launch_bounds__(128) void k_gemm(const float* __restrict__ x,
                                              const float* __restrict__ W) {
    __shared__ __align__(16) unsigned long long sX[KT][BM + 2];  // duplicated {v,v}
    __shared__ __align__(16) float              sW[KT][BN + 4];
    __shared__ int sPix[KT];

    const int u = blockIdx.x;
    if (u >= g_n_units) return;
    const int c    = g_unit_ring[u];
    const int s0   = g_unit_s0[u];
    const int nc   = g_ring_count[c];
    const int send = (s0 + KCHUNK < nc) ? (s0 + KCHUNK) : nc;
    const int nt   = blockIdx.y;
    const int d0   = nt * BN;
    const int t    = threadIdx.x;
    const int td   = t & 15;   // 16 threads over d, 8 each
    const int tb   = t >> 4;   // 8 threads over b, 8 each

    unsigned long long acc[8][4];
#pragma unroll
    for (int i = 0; i < 8; i++)
#pragma unroll
        for (int j = 0; j < 4; j++) acc[i][j] = 0ull;

    for (int s = s0; s < send; s += KT) {
        // pixel indices for this sub-tile
        if (t < KT) {
            int j = s + t;
            sPix[t] = (j < send) ? g_ring_idx[c][j] : -1;
        }
        __syncthreads();
        // gather x (duplicated into f32x2): 32 pixels x 64 batch
        {
            const int j = t & 31;
            const int b0 = t >> 5;
            const int p = sPix[j];
#pragma unroll
            for (int pass = 0; pass < 16; pass++) {
                int b = b0 + pass * 4;
                float v = (p >= 0) ? __ldg(&x[(size_t)b * P + p]) : 0.0f;
                sX[j][b] = pack2(v, v);
            }
        }
        // gather W: 32 pixels x 128 d
        {
            const int j = t & 31;
            const int dl0 = t >> 5;
            const int p = sPix[j];
#pragma unroll
            for (int pass = 0; pass < 32; pass++) {
                int dl = dl0 + pass * 4;
                sW[j][dl] = (p >= 0) ? __ldg(&W[(size_t)(d0 + dl) * P + p]) : 0.0f;
            }
        }
        __syncthreads();
        // compute
#pragma unroll 4
        for (int p = 0; p < KT; p++) {
            const ulonglong2* xrow =
                reinterpret_cast<const ulonglong2*>(&sX[p][tb * 8]);
            ulonglong2 xv0 = xrow[0], xv1 = xrow[1], xv2 = xrow[2], xv3 = xrow[3];
            unsigned long long xr[8] = {xv0.x, xv0.y, xv1.x, xv1.y,
                                        xv2.x, xv2.y, xv3.x, xv3.y};
            const ulonglong2* wrow =
                reinterpret_cast<const ulonglong2*>(&sW[p][td * 8]);
            ulonglong2 wv0 = wrow[0], wv1 = wrow[1];
            unsigned long long wr[4] = {wv0.x, wv0.y, wv1.x, wv1.y};
#pragma unroll
            for (int bi = 0; bi < 8; bi++)
#pragma unroll
                for (int dj = 0; dj < 4; dj++)
                    fma2(acc[bi][dj], xr[bi], wr[dj]);
        }
        __syncthreads();
    }

    // flush partials (deterministic; no atomics)
    float* out = g_part + (size_t)(u * NT + nt) * BM * BN;
#pragma unroll
    for (int bi = 0; bi < 8; bi++) {
        int b = tb * 8 + bi;
        float2 a0 = unpack2(acc[bi][0]);
        float2 a1 = unpack2(acc[bi][1]);
        float2 a2 = unpack2(acc[bi][2]);
        float2 a3 = unpack2(acc[bi][3]);
        float4 v0 = make_float4(a0.x, a0.y, a1.x, a1.y);
        float4 v1 = make_float4(a2.x, a2.y, a3.x, a3.y);
        float4* dst = reinterpret_cast<float4*>(&out[b * BN + td * 8]);
        dst[0] = v0;
        dst[1] = v1;
    }
}

// ---------------- K4: reduce partials -> tokens [b][c][d] ----------------
__global__ __launch_bounds__(256) void k_reduce() {
    int i = blockIdx.x * 256 + threadIdx.x;
    if (i >= NB * NR * TD) return;
    int d  = i & (TD - 1);
    int c  = (i >> 8) & (NR - 1);
    int b  = i >> 12;
    int nt = d >> 7;
    int dl = d & (BN - 1);
    float s = 0.0f;
    int u0 = g_ring_ustart[c], u1 = g_ring_uend[c];
    for (int u = u0; u < u1; u++)
        s += g_part[((size_t)(u * NT + nt) * BM + b) * BN + dl];
    g_tokens[i] = s;
}

// ---------------- K5: fc layer  out[m][o] = tokens[m,:] @ fc_w[o,:] + fc_b[o] ----
// M = 1024 (b*16+c), N = 192, K = 256. grid (16,3), block 256, thread tile 4x4.
__global__ __launch_bounds__(256) void k_fc(const float* __restrict__ fcw,
                                            const float* __restrict__ fcb,
                                            float* __restrict__ out) {
    __shared__ __align__(16) float sT[32][68];
    __shared__ __align__(16) float sF[32][68];
    const int m0 = blockIdx.x * 64;
    const int n0 = blockIdx.y * 64;
    const int t  = threadIdx.x;
    const int td = t & 15;   // n, 4 each
    const int tb = t >> 4;   // m, 4 each
    float acc[4][4];
#pragma unroll
    for (int i = 0; i < 4; i++)
#pragma unroll
        for (int j = 0; j < 4; j++) acc[i][j] = 0.0f;

    for (int k0 = 0; k0 < TD; k0 += 32) {
        const int j  = t & 31;
        const int r0 = t >> 5;
#pragma unroll
        for (int pass = 0; pass < 8; pass++) {
            int r = r0 + pass * 8;
            sT[j][r] = g_tokens[(size_t)(m0 + r) * TD + k0 + j];
            sF[j][r] = fcw[(size_t)(n0 + r) * TD + k0 + j];
        }
        __syncthreads();
#pragma unroll
        for (int p = 0; p < 32; p++) {
            float4 tv = *reinterpret_cast<const float4*>(&sT[p][tb * 4]);
            float4 fv = *reinterpret_cast<const float4*>(&sF[p][td * 4]);
            float tx[4] = {tv.x, tv.y, tv.z, tv.w};
            float fx[4] = {fv.x, fv.y, fv.z, fv.w};
#pragma unroll
            for (int i = 0; i < 4; i++)
#pragma unroll
                for (int jj = 0; jj < 4; jj++)
                    acc[i][jj] += tx[i] * fx[jj];
        }
        __syncthreads();
    }
#pragma unroll
    for (int i = 0; i < 4; i++) {
        int m = m0 + tb * 4 + i;
#pragma unroll
        for (int jj = 0; jj < 4; jj++) {
            int o = n0 + td * 4 + jj;
            out[(size_t)m * OD + o] = acc[i][jj] + fcb[o];
        }
    }
}

// ---------------- launch ----------------
extern "C" void kernel_launch(void* const* d_in, const int* in_sizes, int n_in,
                              void* d_out, int out_size) {
    const float *x = nullptr, *tw = nullptr, *fcw = nullptr, *fcb = nullptr,
                *masks = nullptr;
    // map inputs by (unique) element counts, falling back to positional order
    for (int i = 0; i < n_in; i++) {
        switch (in_sizes[i]) {
            case NB * P:       x     = (const float*)d_in[i]; break;   // 3,211,264
            case TD * P:       tw    = (const float*)d_in[i]; break;   // 12,845,056
            case OD * TD:      fcw   = (const float*)d_in[i]; break;   // 49,152
            case OD:           fcb   = (const float*)d_in[i]; break;   // 192
            case NR * P:       masks = (const float*)d_in[i]; break;   // 802,816
            default: break;
        }
    }
    if (!x)     x     = (const float*)d_in[0];
    if (!tw)    tw    = (const float*)d_in[1];
    if (!fcw)   fcw   = (const float*)d_in[2];
    if (!fcb)   fcb   = (const float*)d_in[3];
    if (!masks) masks = (const float*)d_in[4];
    float* out = (float*)d_out;

    k_build_rings<<<NR, 1024>>>(masks);
    k_build_units<<<1, 1>>>();
    k_gemm<<<dim3(MAXU, NT), 128>>>(x, tw);
    k_reduce<<<(NB * NR * TD + 255) / 256, 256>>>();
    k_fc<<<dim3(NB * NR / 64, OD / 64), 256>>>(fcw, fcb, out);
}

// round 4
// speedup vs baseline: 1.5821x; 1.5821x over previous
#include <cuda_runtime.h>
#include <cstdint>

// ---------------- problem constants ----------------
#define IMG      224
#define P        (IMG*IMG)          // 50176
#define NB       64
#define NR       16
#define TD       256
#define OD       192

// ---------------- tiling ----------------
#define RING_CAP 5120
#define KCHUNK   128                   // pixels per block
#define KT       16                    // K sub-tile (pipeline stage)
#define UPR      (RING_CAP / KCHUNK)   // 40
#define MAXU     (NR * UPR)            // 640
#define BM       64
#define BN       256
#define SWP      260                   // sW row pitch (floats): 16B aligned, bank-stagger
#define SXP      68                    // sX row pitch (floats)

typedef unsigned long long ull;

// ---------------- device scratch ----------------
__device__ int   g_ring_idx[NR][RING_CAP];
__device__ int   g_ring_count[NR];
__device__ float g_part[(size_t)MAXU * BM * BN];   // 41.9 MB partials
__device__ float g_tokens[NB * NR * TD];

// ---------------- helpers ----------------
__device__ __forceinline__ ull dup2(float v) {
    ull r; asm("mov.b64 %0, {%1, %1};" : "=l"(r) : "f"(v)); return r;
}
__device__ __forceinline__ float2 unpack2(ull v) {
    float2 f; asm("mov.b64 {%0, %1}, %2;" : "=f"(f.x), "=f"(f.y) : "l"(v)); return f;
}
__device__ __forceinline__ void fma2(ull& acc, ull a, ull b) {
    asm("fma.rn.f32x2 %0, %1, %2, %0;" : "+l"(acc) : "l"(a), "l"(b));
}
__device__ __forceinline__ void cpasync4(uint32_t saddr, const void* gaddr) {
    asm volatile("cp.async.ca.shared.global [%0], [%1], 4;" :: "r"(saddr), "l"(gaddr));
}
__device__ __forceinline__ void cpasync_commit() {
    asm volatile("cp.async.commit_group;");
}
__device__ __forceinline__ void cpasync_wait_all() {
    asm volatile("cp.async.wait_group 0;");
}

// ---------------- K1: per-ring stable pixel lists ----------------
__global__ __launch_bounds__(1024) void k_build_rings(const float* __restrict__ masks) {
    const int c = blockIdx.x;
    const float* m = masks + (size_t)c * P;
    __shared__ int s_cnt[32];
    __shared__ int s_off[32];
    const int lane = threadIdx.x & 31;
    const int warp = threadIdx.x >> 5;
    const int base = warp * (P / 32);
    const int iters = P / 1024;

    int cnt = 0;
    for (int it = 0; it < iters; it++) {
        int p = base + it * 32 + lane;
        unsigned bl = __ballot_sync(0xFFFFFFFFu, m[p] != 0.0f);
        cnt += __popc(bl);
    }
    if (lane == 0) s_cnt[warp] = cnt;
    __syncthreads();
    if (warp == 0) {
        int v = s_cnt[lane];
        int sum = v;
#pragma unroll
        for (int d = 1; d < 32; d <<= 1) {
            int o = __shfl_up_sync(0xFFFFFFFFu, sum, d);
            if (lane >= d) sum += o;
        }
        s_off[lane] = sum - v;
        if (lane == 31) g_ring_count[c] = (sum < RING_CAP) ? sum : RING_CAP;
    }
    __syncthreads();
    int off = s_off[warp];
    const unsigned lmask = (1u << lane) - 1u;
    for (int it = 0; it < iters; it++) {
        int p = base + it * 32 + lane;
        bool in = (m[p] != 0.0f);
        unsigned bl = __ballot_sync(0xFFFFFFFFu, in);
        if (in) {
            int rank = off + __popc(bl & lmask);
            if (rank < RING_CAP) g_ring_idx[c][rank] = p;
        }
        off += __popc(bl);
    }
}

// ---------------- K2: segmented GEMM (static smem, f32x2) ----------------
// grid (UPR, NR), 256 threads. BM=64 x BN=256 per block, KCHUNK=128 pixels.
__global__ __launch_bounds__(256, 2) void k_gemm(const float* __restrict__ x,
                                                 const float* __restrict__ W) {
    __shared__ __align__(16) float sW[2][KT][SWP];   // 33.3 KB
    __shared__ __align__(16) float sX[2][KT][SXP];   //  8.7 KB

    const int c  = blockIdx.y;
    const int nc = g_ring_count[c];
    const int s0 = blockIdx.x * KCHUNK;
    if (s0 >= nc) return;
    const int send = (s0 + KCHUNK < nc) ? (s0 + KCHUNK) : nc;
    const int nT   = (send - s0 + KT - 1) / KT;

    const int t    = threadIdx.x;
    const int lane = t & 31;
    const int w    = t >> 5;

    // loader roles: j = pixel-in-tile (16), dg = d-group of 16, bg = b-group of 4
    const int j  = t & 15;
    const int dg = t >> 4;          // 0..15
    const int bg = t >> 4;          // 0..15 (b = bg*4 + i)

    const uint32_t swbase = (uint32_t)__cvta_generic_to_shared(&sW[0][0][0]);
    const int* ridx = g_ring_idx[c];

    float rx[4];
    // load x of tile tl into regs
    auto loadX = [&](int tl) {
        int jj = s0 + tl * KT + j;
        int p  = (jj < send) ? ridx[jj] : -1;
        if (p >= 0) {
#pragma unroll
            for (int i = 0; i < 4; i++)
                rx[i] = __ldg(&x[(size_t)(bg * 4 + i) * P + p]);
        } else {
#pragma unroll
            for (int i = 0; i < 4; i++) rx[i] = 0.0f;
        }
    };
    auto stsX = [&](int buf) {
        float4* dst = (float4*)&sX[buf][j][bg * 4];
        *dst = make_float4(rx[0], rx[1], rx[2], rx[3]);
    };
    // async gather W of tile tl
    auto issueW = [&](int buf, int tl) {
        int jj = s0 + tl * KT + j;
        int p  = (jj < send) ? ridx[jj] : 0;     // pad pixels: x zeroed, W junk harmless
        if (p < 0) p = 0;
        const float* g = &W[(size_t)(dg * 16) * P + p];
        uint32_t d = swbase + (uint32_t)((buf * KT + j) * SWP + dg * 16) * 4u;
#pragma unroll
        for (int i = 0; i < 16; i++) {
            cpasync4(d, g);
            g += (size_t)P;
            d += 4;
        }
    };

    // compute mapping: warp -> (b half, d quarter); lane -> 8b x 8d tile
    const int bw = w & 1, dw = w >> 1;
    const int lb = lane & 3, ld = lane >> 2;
    const int b_base = bw * 32 + lb * 8;
    const int d_base = dw * 64 + ld * 8;

    ull acc[8][4];
#pragma unroll
    for (int i = 0; i < 8; i++)
#pragma unroll
        for (int jj2 = 0; jj2 < 4; jj2++) acc[i][jj2] = 0ull;

    auto compute = [&](int buf) {
#pragma unroll
        for (int p = 0; p < KT; p++) {
            const float4* xr4 = (const float4*)&sX[buf][p][b_base];
            float4 xa = xr4[0], xb2 = xr4[1];
            ull xr[8];
            xr[0] = dup2(xa.x); xr[1] = dup2(xa.y);
            xr[2] = dup2(xa.z); xr[3] = dup2(xa.w);
            xr[4] = dup2(xb2.x); xr[5] = dup2(xb2.y);
            xr[6] = dup2(xb2.z); xr[7] = dup2(xb2.w);
            const ulonglong2* wr2 = (const ulonglong2*)&sW[buf][p][d_base];
            ulonglong2 wv0 = wr2[0], wv1 = wr2[1];
            ull wr[4] = {wv0.x, wv0.y, wv1.x, wv1.y};
#pragma unroll
            for (int bi = 0; bi < 8; bi++)
#pragma unroll
                for (int dj = 0; dj < 4; dj++)
                    fma2(acc[bi][dj], xr[bi], wr[dj]);
        }
    };

    // ---- software pipeline ----
    loadX(0);
    issueW(0, 0);
    cpasync_commit();
    stsX(0);
    cpasync_wait_all();
    __syncthreads();

    for (int tl = 0; tl < nT; tl++) {
        const int cur = tl & 1, nxt = cur ^ 1;
        const bool more = (tl + 1 < nT);
        if (more) {
            loadX(tl + 1);
            issueW(nxt, tl + 1);
            cpasync_commit();
        }
        compute(cur);
        if (more) {
            stsX(nxt);
            cpasync_wait_all();
        }
        __syncthreads();
    }

    // ---- flush partials ----
    const int u = c * UPR + blockIdx.x;
    float* outp = g_part + (size_t)u * BM * BN;
#pragma unroll
    for (int bi = 0; bi < 8; bi++) {
        int b = b_base + bi;
        float2 f0 = unpack2(acc[bi][0]);
        float2 f1 = unpack2(acc[bi][1]);
        float2 f2 = unpack2(acc[bi][2]);
        float2 f3 = unpack2(acc[bi][3]);
        float4* dst = (float4*)&outp[(size_t)b * BN + d_base];
        dst[0] = make_float4(f0.x, f0.y, f1.x, f1.y);
        dst[1] = make_float4(f2.x, f2.y, f3.x, f3.y);
    }
}

// ---------------- K3: reduce partials -> tokens ----------------
__global__ __launch_bounds__(256) void k_reduce() {
    int i = blockIdx.x * 256 + threadIdx.x;           // 65536 threads, float4 each
    int d4   = i & 63;
    int ring = (i >> 6) & 15;
    int b    = i >> 10;
    int ua = (g_ring_count[ring] + KCHUNK - 1) / KCHUNK;
    const float4* base = (const float4*)g_part;
    size_t idx = (size_t)(ring * UPR) * (BM * BN / 4) + (size_t)b * (BN / 4) + d4;
    float4 s = make_float4(0.f, 0.f, 0.f, 0.f);
    for (int u = 0; u < ua; u++) {
        float4 v = base[idx + (size_t)u * (BM * BN / 4)];
        s.x += v.x; s.y += v.y; s.z += v.z; s.w += v.w;
    }
    ((float4*)g_tokens)[(size_t)b * (NR * TD / 4) + ring * (TD / 4) + d4] = s;
}

// ---------------- K4: fc ----------------
__global__ __launch_bounds__(256) void k_fc(const float* __restrict__ fcw,
                                            const float* __restrict__ fcb,
                                            float* __restrict__ out) {
    __shared__ __align__(16) float sT[32][68];
    __shared__ __align__(16) float sF[32][68];
    const int m0 = blockIdx.x * 64;
    const int n0 = blockIdx.y * 64;
    const int t  = threadIdx.x;
    const int td = t & 15;
    const int tb = t >> 4;
    float acc[4][4];
#pragma unroll
    for (int i = 0; i < 4; i++)
#pragma unroll
        for (int jj = 0; jj < 4; jj++) acc[i][jj] = 0.0f;

    for (int k0 = 0; k0 < TD; k0 += 32) {
        const int j  = t & 31;
        const int r0 = t >> 5;
#pragma unroll
        for (int pass = 0; pass < 8; pass++) {
            int r = r0 + pass * 8;
            sT[j][r] = g_tokens[(size_t)(m0 + r) * TD + k0 + j];
            sF[j][r] = fcw[(size_t)(n0 + r) * TD + k0 + j];
        }
        __syncthreads();
#pragma unroll
        for (int p = 0; p < 32; p++) {
            float4 tv = *(const float4*)&sT[p][tb * 4];
            float4 fv = *(const float4*)&sF[p][td * 4];
            float tx[4] = {tv.x, tv.y, tv.z, tv.w};
            float fx[4] = {fv.x, fv.y, fv.z, fv.w};
#pragma unroll
            for (int i = 0; i < 4; i++)
#pragma unroll
                for (int jj = 0; jj < 4; jj++)
                    acc[i][jj] += tx[i] * fx[jj];
        }
        __syncthreads();
    }
#pragma unroll
    for (int i = 0; i < 4; i++) {
        int m = m0 + tb * 4 + i;
#pragma unroll
        for (int jj = 0; jj < 4; jj++) {
            int o = n0 + td * 4 + jj;
            out[(size_t)m * OD + o] = acc[i][jj] + fcb[o];
        }
    }
}

// ---------------- launch ----------------
extern "C" void kernel_launch(void* const* d_in, const int* in_sizes, int n_in,
                              void* d_out, int out_size) {
    const float *x = nullptr, *tw = nullptr, *fcw = nullptr, *fcb = nullptr,
                *masks = nullptr;
    for (int i = 0; i < n_in; i++) {
        switch (in_sizes[i]) {
            case NB * P:  x     = (const float*)d_in[i]; break;
            case TD * P:  tw    = (const float*)d_in[i]; break;
            case OD * TD: fcw   = (const float*)d_in[i]; break;
            case OD:      fcb   = (const float*)d_in[i]; break;
            case NR * P:  masks = (const float*)d_in[i]; break;
            default: break;
        }
    }
    if (!x)     x     = (const float*)d_in[0];
    if (!tw)    tw    = (const float*)d_in[1];
    if (!fcw)   fcw   = (const float*)d_in[2];
    if (!fcb)   fcb   = (const float*)d_in[3];
    if (!masks) masks = (const float*)d_in[4];
    float* out = (float*)d_out;

    k_build_rings<<<NR, 1024>>>(masks);
    k_gemm<<<dim3(UPR, NR), 256>>>(x, tw);
    k_reduce<<<256, 256>>>();
    k_fc<<<dim3(NB * NR / 64, OD / 64), 256>>>(fcw, fcb, out);
}

// round 5
// speedup vs baseline: 1.9424x; 1.2277x over previous
#include <cuda_runtime.h>
#include <cstdint>

// ---------------- problem constants ----------------
#define IMG      224
#define P        (IMG*IMG)          // 50176
#define NB       64
#define NR       16
#define TD       256
#define OD       192

// ---------------- tiling ----------------
#define RING_CAP 5120
#define KCHUNK   144                   // pixels per block (283 active blocks -> 1 wave)
#define KT       16                    // K sub-tile (pipeline stage)
#define UPR      ((RING_CAP + KCHUNK - 1) / KCHUNK)   // 36
#define MAXU     (NR * UPR)            // 576
#define BM       64
#define BN       256
#define SWP      260                   // sW row pitch (floats)
#define SXP      68                    // sX row pitch (floats)

typedef unsigned long long ull;

// ---------------- device scratch ----------------
__device__ int   g_ring_idx[NR][RING_CAP];
__device__ int   g_ring_count[NR];
__device__ float g_part[(size_t)MAXU * BM * BN];   // 37.7 MB partials
__device__ float g_tokens[NB * NR * TD];

// ---------------- helpers ----------------
__device__ __forceinline__ ull dup2(float v) {
    ull r; asm("mov.b64 %0, {%1, %1};" : "=l"(r) : "f"(v)); return r;
}
__device__ __forceinline__ float2 unpack2(ull v) {
    float2 f; asm("mov.b64 {%0, %1}, %2;" : "=f"(f.x), "=f"(f.y) : "l"(v)); return f;
}
__device__ __forceinline__ void fma2(ull& acc, ull a, ull b) {
    asm("fma.rn.f32x2 %0, %1, %2, %0;" : "+l"(acc) : "l"(a), "l"(b));
}
__device__ __forceinline__ void cpasync4(uint32_t saddr, const void* gaddr) {
    asm volatile("cp.async.ca.shared.global [%0], [%1], 4;" :: "r"(saddr), "l"(gaddr));
}
__device__ __forceinline__ void cpasync_commit() {
    asm volatile("cp.async.commit_group;");
}
__device__ __forceinline__ void cpasync_wait_all() {
    asm volatile("cp.async.wait_group 0;");
}

// ---------------- K1: per-ring stable pixel lists (pipelined) ----------------
// 49 iterations split as 7 batches of 7 prefetched values.
__global__ __launch_bounds__(1024) void k_build_rings(const float* __restrict__ masks) {
    const int c = blockIdx.x;
    const float* m = masks + (size_t)c * P;
    __shared__ int s_cnt[32];
    __shared__ int s_off[32];
    const int lane = threadIdx.x & 31;
    const int warp = threadIdx.x >> 5;
    const int base = warp * (P / 32);       // 1568 contiguous pixels per warp

    // --- count pass: no ballots, loads fully pipelined ---
    int cnt = 0;
#pragma unroll 7
    for (int it = 0; it < 49; it++) {
        cnt += (m[base + it * 32 + lane] != 0.0f) ? 1 : 0;
    }
#pragma unroll
    for (int d = 16; d >= 1; d >>= 1)
        cnt += __shfl_xor_sync(0xFFFFFFFFu, cnt, d);
    if (lane == 0) s_cnt[warp] = cnt;
    __syncthreads();
    if (warp == 0) {
        int v = s_cnt[lane];
        int sum = v;
#pragma unroll
        for (int d = 1; d < 32; d <<= 1) {
            int o = __shfl_up_sync(0xFFFFFFFFu, sum, d);
            if (lane >= d) sum += o;
        }
        s_off[lane] = sum - v;
        if (lane == 31) g_ring_count[c] = (sum < RING_CAP) ? sum : RING_CAP;
    }
    __syncthreads();

    // --- write pass: prefetch 7 values, then 7 ballot+scatter steps ---
    int off = s_off[warp];
    const unsigned lmask = (1u << lane) - 1u;
    for (int bt = 0; bt < 7; bt++) {
        float v[7];
#pragma unroll
        for (int i = 0; i < 7; i++)
            v[i] = m[base + (bt * 7 + i) * 32 + lane];
#pragma unroll
        for (int i = 0; i < 7; i++) {
            bool in = (v[i] != 0.0f);
            unsigned bl = __ballot_sync(0xFFFFFFFFu, in);
            if (in) {
                int rank = off + __popc(bl & lmask);
                if (rank < RING_CAP) g_ring_idx[c][rank] = base + (bt * 7 + i) * 32 + lane;
            }
            off += __popc(bl);
        }
    }
}

// ---------------- K2: segmented GEMM (static smem, f32x2) ----------------
__global__ __launch_bounds__(256, 2) void k_gemm(const float* __restrict__ x,
                                                 const float* __restrict__ W) {
    __shared__ __align__(16) float sW[2][KT][SWP];   // 33.3 KB
    __shared__ __align__(16) float sX[2][KT][SXP];   //  8.7 KB

    const int c  = blockIdx.y;
    const int nc = g_ring_count[c];
    const int s0 = blockIdx.x * KCHUNK;
    if (s0 >= nc) return;
    const int send = (s0 + KCHUNK < nc) ? (s0 + KCHUNK) : nc;
    const int nT   = (send - s0 + KT - 1) / KT;

    const int t    = threadIdx.x;
    const int lane = t & 31;
    const int w    = t >> 5;

    const int j  = t & 15;
    const int dg = t >> 4;
    const int bg = t >> 4;

    const uint32_t swbase = (uint32_t)__cvta_generic_to_shared(&sW[0][0][0]);
    const int* ridx = g_ring_idx[c];

    float rx[4];
    auto loadX = [&](int tl) {
        int jj = s0 + tl * KT + j;
        int p  = (jj < send) ? ridx[jj] : -1;
        if (p >= 0) {
#pragma unroll
            for (int i = 0; i < 4; i++)
                rx[i] = __ldg(&x[(size_t)(bg * 4 + i) * P + p]);
        } else {
#pragma unroll
            for (int i = 0; i < 4; i++) rx[i] = 0.0f;
        }
    };
    auto stsX = [&](int buf) {
        float4* dst = (float4*)&sX[buf][j][bg * 4];
        *dst = make_float4(rx[0], rx[1], rx[2], rx[3]);
    };
    auto issueW = [&](int buf, int tl) {
        int jj = s0 + tl * KT + j;
        int p  = (jj < send) ? ridx[jj] : 0;
        if (p < 0) p = 0;
        const float* g = &W[(size_t)(dg * 16) * P + p];
        uint32_t d = swbase + (uint32_t)((buf * KT + j) * SWP + dg * 16) * 4u;
#pragma unroll
        for (int i = 0; i < 16; i++) {
            cpasync4(d, g);
            g += (size_t)P;
            d += 4;
        }
    };

    const int bw = w & 1, dw = w >> 1;
    const int lb = lane & 3, ld = lane >> 2;
    const int b_base = bw * 32 + lb * 8;
    const int d_base = dw * 64 + ld * 8;

    ull acc[8][4];
#pragma unroll
    for (int i = 0; i < 8; i++)
#pragma unroll
        for (int jj2 = 0; jj2 < 4; jj2++) acc[i][jj2] = 0ull;

    auto compute = [&](int buf) {
#pragma unroll
        for (int p = 0; p < KT; p++) {
            const float4* xr4 = (const float4*)&sX[buf][p][b_base];
            float4 xa = xr4[0], xb2 = xr4[1];
            ull xr[8];
            xr[0] = dup2(xa.x); xr[1] = dup2(xa.y);
            xr[2] = dup2(xa.z); xr[3] = dup2(xa.w);
            xr[4] = dup2(xb2.x); xr[5] = dup2(xb2.y);
            xr[6] = dup2(xb2.z); xr[7] = dup2(xb2.w);
            const ulonglong2* wr2 = (const ulonglong2*)&sW[buf][p][d_base];
            ulonglong2 wv0 = wr2[0], wv1 = wr2[1];
            ull wr[4] = {wv0.x, wv0.y, wv1.x, wv1.y};
#pragma unroll
            for (int bi = 0; bi < 8; bi++)
#pragma unroll
                for (int dj = 0; dj < 4; dj++)
                    fma2(acc[bi][dj], xr[bi], wr[dj]);
        }
    };

    loadX(0);
    issueW(0, 0);
    cpasync_commit();
    stsX(0);
    cpasync_wait_all();
    __syncthreads();

    for (int tl = 0; tl < nT; tl++) {
        const int cur = tl & 1, nxt = cur ^ 1;
        const bool more = (tl + 1 < nT);
        if (more) {
            loadX(tl + 1);
            issueW(nxt, tl + 1);
            cpasync_commit();
        }
        compute(cur);
        if (more) {
            stsX(nxt);
            cpasync_wait_all();
        }
        __syncthreads();
    }

    const int u = c * UPR + blockIdx.x;
    float* outp = g_part + (size_t)u * BM * BN;
#pragma unroll
    for (int bi = 0; bi < 8; bi++) {
        int b = b_base + bi;
        float2 f0 = unpack2(acc[bi][0]);
        float2 f1 = unpack2(acc[bi][1]);
        float2 f2 = unpack2(acc[bi][2]);
        float2 f3 = unpack2(acc[bi][3]);
        float4* dst = (float4*)&outp[(size_t)b * BN + d_base];
        dst[0] = make_float4(f0.x, f0.y, f1.x, f1.y);
        dst[1] = make_float4(f2.x, f2.y, f3.x, f3.y);
    }
}

// ---------------- K3: reduce partials -> tokens ----------------
__global__ __launch_bounds__(256) void k_reduce() {
    int i = blockIdx.x * 256 + threadIdx.x;           // 65536 threads, float4 each
    int d4   = i & 63;
    int ring = (i >> 6) & 15;
    int b    = i >> 10;
    int ua = (g_ring_count[ring] + KCHUNK - 1) / KCHUNK;
    const float4* base = (const float4*)g_part;
    size_t idx = (size_t)(ring * UPR) * (BM * BN / 4) + (size_t)b * (BN / 4) + d4;
    float4 s = make_float4(0.f, 0.f, 0.f, 0.f);
    for (int u = 0; u < ua; u++) {
        float4 v = base[idx + (size_t)u * (BM * BN / 4)];
        s.x += v.x; s.y += v.y; s.z += v.z; s.w += v.w;
    }
    ((float4*)g_tokens)[(size_t)b * (NR * TD / 4) + ring * (TD / 4) + d4] = s;
}

// ---------------- K4: fc  out[m][o] = tokens[m,:] @ fc_w[o,:] + b --------------
// grid (32, 3), 256 threads. Tile 32m x 64n; thread 2m x 4n with f32x2.
__global__ __launch_bounds__(256) void k_fc(const float* __restrict__ fcw,
                                            const float* __restrict__ fcb,
                                            float* __restrict__ out) {
    __shared__ __align__(16) float sT[32][68];    // [m][k] chunk
    __shared__ __align__(16) float sF[64][68];    // [k][n] chunk (transposed)
    const int m0 = blockIdx.x * 32;
    const int n0 = blockIdx.y * 64;
    const int t  = threadIdx.x;

    const int tm2 = (t >> 4) * 2;        // 2 m rows
    const int n4  = (t & 15) * 4;        // 4 n cols

    ull acc[2][2];
    acc[0][0] = acc[0][1] = acc[1][0] = acc[1][1] = 0ull;

    for (int k0 = 0; k0 < TD; k0 += 64) {
        // load tokens tile: 32 rows x 64 k
        {
            int r  = t >> 3;             // 32 rows, 8 threads each
            int kk = (t & 7) * 8;
            const float4* src = (const float4*)&g_tokens[(size_t)(m0 + r) * TD + k0 + kk];
            float4 a = src[0], b2 = src[1];
            *(float4*)&sT[r][kk]     = a;
            *(float4*)&sT[r][kk + 4] = b2;
        }
        // load fcw tile transposed: 64 n rows x 64 k -> sF[k][n]
        {
            int r  = t >> 2;             // 64 n rows, 4 threads each
            int kk = (t & 3) * 16;
            const float4* src = (const float4*)&fcw[(size_t)(n0 + r) * TD + k0 + kk];
#pragma unroll
            for (int q = 0; q < 4; q++) {
                float4 v = src[q];
                sF[kk + q * 4 + 0][r] = v.x;
                sF[kk + q * 4 + 1][r] = v.y;
                sF[kk + q * 4 + 2][r] = v.z;
                sF[kk + q * 4 + 3][r] = v.w;
            }
        }
        __syncthreads();
#pragma unroll 8
        for (int k = 0; k < 64; k++) {
            ull xv0 = dup2(sT[tm2][k]);
            ull xv1 = dup2(sT[tm2 + 1][k]);
            ulonglong2 wv = *(const ulonglong2*)&sF[k][n4];
            fma2(acc[0][0], xv0, wv.x);
            fma2(acc[0][1], xv0, wv.y);
            fma2(acc[1][0], xv1, wv.x);
            fma2(acc[1][1], xv1, wv.y);
        }
        __syncthreads();
    }

    float4 bias = make_float4(fcb[n0 + n4], fcb[n0 + n4 + 1],
                              fcb[n0 + n4 + 2], fcb[n0 + n4 + 3]);
#pragma unroll
    for (int i = 0; i < 2; i++) {
        float2 a0 = unpack2(acc[i][0]);
        float2 a1 = unpack2(acc[i][1]);
        float4 v = make_float4(a0.x + bias.x, a0.y + bias.y,
                               a1.x + bias.z, a1.y + bias.w);
        *(float4*)&out[(size_t)(m0 + tm2 + i) * OD + n0 + n4] = v;
    }
}

// ---------------- launch ----------------
extern "C" void kernel_launch(void* const* d_in, const int* in_sizes, int n_in,
                              void* d_out, int out_size) {
    const float *x = nullptr, *tw = nullptr, *fcw = nullptr, *fcb = nullptr,
                *masks = nullptr;
    for (int i = 0; i < n_in; i++) {
        switch (in_sizes[i]) {
            case NB * P:  x     = (const float*)d_in[i]; break;
            case TD * P:  tw    = (const float*)d_in[i]; break;
            case OD * TD: fcw   = (const float*)d_in[i]; break;
            case OD:      fcb   = (const float*)d_in[i]; break;
            case NR * P:  masks = (const float*)d_in[i]; break;
            default: break;
        }
    }
    if (!x)     x     = (const float*)d_in[0];
    if (!tw)    tw    = (const float*)d_in[1];
    if (!fcw)   fcw   = (const float*)d_in[2];
    if (!fcb)   fcb   = (const float*)d_in[3];
    if (!masks) masks = (const float*)d_in[4];
    float* out = (float*)d_out;

    k_build_rings<<<NR, 1024>>>(masks);
    k_gemm<<<dim3(UPR, NR), 256>>>(x, tw);
    k_reduce<<<256, 256>>>();
    k_fc<<<dim3(NB * NR / 32, OD / 64), 256>>>(fcw, fcb, out);
}